// round 5
// baseline (speedup 1.0000x reference)
#include <cuda_runtime.h>
#include <cuda_bf16.h>
#include <cstdint>

// Problem constants
constexpr int Bn = 8192;   // batch
constexpr int Dn = 1024;   // input dim (K1)
constexpr int Hn = 400;    // hidden
constexpr int Ln = 256;    // half output
constexpr int En = 16;     // experts
constexpr int K2n = 512;   // 2L (N of GEMM2)
constexpr int HP = 448;    // hidden padded to 64 (K of GEMM2)
constexpr int NW = 512;    // padded N rows for transposed weights

#define TILE_M 128
#define MAX_TILES 96       // >= B/128 + E = 80
#define QMAX 16256.0f      // 127*128

// ================= device scratch (zero-init, no allocs) =================
__device__ int   g_counts[En];
__device__ int   g_offsets[En + 1];
__device__ int   g_cursor[En];
__device__ int   g_is64;
__device__ int   g_angle[Bn];
__device__ int   g_idx_sorted[Bn + TILE_M];
__device__ int   g_tile_expert[MAX_TILES];
__device__ int   g_tile_rowstart[MAX_TILES];
__device__ int   g_tile_rows[MAX_TILES];

// int8 two-level quantized x and W1t
__device__ char  g_x1[(size_t)Bn * Dn];                    // hi int8 [Bn][1024]
__device__ char  g_x2[(size_t)Bn * Dn];                    // lo int8
__device__ float g_sa[Bn];                                 // per-row x scale
__device__ char  g_w1q1[(size_t)En * NW * Dn];             // [E][512][1024] (n,k)
__device__ char  g_w1q2[(size_t)En * NW * Dn];
__device__ float g_sw1[En * NW];                           // per-(e,n) W1 scale
__device__ float g_invw1[En * NW];

// bf16 hi/lo for GEMM2 path
__device__ uint4 g_w2t_hi[(size_t)En * NW * HP / 8];       // [E][512][448] (n,k)
__device__ uint4 g_w2t_lo[(size_t)En * NW * HP / 8];
__device__ uint4 g_h1_hi[(size_t)(Bn + TILE_M) * HP / 8];  // [rows][448]
__device__ uint4 g_h1_lo[(size_t)(Bn + TILE_M) * HP / 8];

// ================= helpers =================
__device__ __forceinline__ uint32_t smem_u32(const void* p) {
    uint32_t a;
    asm("{ .reg .u64 t; cvta.to.shared.u64 t, %1; cvt.u32.u64 %0, t; }" : "=r"(a) : "l"(p));
    return a;
}

#define CP16(dst_u32, src_ptr) \
    asm volatile("cp.async.cg.shared.global [%0], [%1], 16;" :: "r"(dst_u32), "l"(src_ptr))
#define CP_COMMIT() asm volatile("cp.async.commit_group;" ::: "memory")
#define CP_WAIT1()  asm volatile("cp.async.wait_group 1;" ::: "memory")
#define CP_WAIT0()  asm volatile("cp.async.wait_group 0;" ::: "memory")

__device__ __forceinline__ void mma16816(float* d, const uint32_t* a, const uint32_t* b) {
    asm volatile(
        "mma.sync.aligned.m16n8k16.row.col.f32.bf16.bf16.f32 "
        "{%0,%1,%2,%3}, {%4,%5,%6,%7}, {%8,%9}, {%0,%1,%2,%3};"
        : "+f"(d[0]), "+f"(d[1]), "+f"(d[2]), "+f"(d[3])
        : "r"(a[0]), "r"(a[1]), "r"(a[2]), "r"(a[3]), "r"(b[0]), "r"(b[1]));
}

__device__ __forceinline__ void imma16832(int* d, const uint32_t* a, const uint32_t* b) {
    asm volatile(
        "mma.sync.aligned.m16n8k32.row.col.s32.s8.s8.s32 "
        "{%0,%1,%2,%3}, {%4,%5,%6,%7}, {%8,%9}, {%0,%1,%2,%3};"
        : "+r"(d[0]), "+r"(d[1]), "+r"(d[2]), "+r"(d[3])
        : "r"(a[0]), "r"(a[1]), "r"(a[2]), "r"(a[3]), "r"(b[0]), "r"(b[1]));
}

__device__ __forceinline__ void split2(float v0, float v1, uint32_t& hi, uint32_t& lo) {
    __nv_bfloat16 h0 = __float2bfloat16(v0);
    __nv_bfloat16 h1 = __float2bfloat16(v1);
    __nv_bfloat16 l0 = __float2bfloat16(v0 - __bfloat162float(h0));
    __nv_bfloat16 l1 = __float2bfloat16(v1 - __bfloat162float(h1));
    __nv_bfloat162 ph; ph.x = h0; ph.y = h1;
    __nv_bfloat162 pl; pl.x = l0; pl.y = l1;
    hi = *reinterpret_cast<uint32_t*>(&ph);
    lo = *reinterpret_cast<uint32_t*>(&pl);
}

// q in [-16256,16256] -> (q1, q2) with q = 128*q1 + q2
__device__ __forceinline__ void qsplit(float v, float inv, char& c1, char& c2) {
    float q = rintf(v * inv);
    int q1 = (int)rintf(q * (1.0f / 128.0f));
    int q2 = (int)q - 128 * q1;
    c1 = (char)q1;
    c2 = (char)q2;
}

// ================= prep kernels =================
__global__ void reset_kernel() {
    int t = threadIdx.x;
    if (t < En) { g_counts[t] = 0; g_cursor[t] = 0; }
    if (t == 0) g_is64 = 1;
    if (t < TILE_M) g_idx_sorted[Bn + t] = 0;
}

__global__ void detect_kernel(const long long* __restrict__ ai) {
    int t = blockIdx.x * blockDim.x + threadIdx.x;
    if (t < Bn / 2) {
        long long v = ai[t];
        if (v < 0 || v >= En) g_is64 = 0;
    }
}

__global__ void convert_count_kernel(const void* __restrict__ ai) {
    int t = blockIdx.x * blockDim.x + threadIdx.x;
    if (t < Bn) {
        int v = g_is64 ? (int)((const long long*)ai)[t] : ((const int*)ai)[t];
        g_angle[t] = v;
        atomicAdd(&g_counts[v], 1);
    }
}

__global__ void prefix_kernel() {
    if (threadIdx.x == 0) {
        int off = 0;
        for (int e = 0; e < En; e++) { g_offsets[e] = off; off += g_counts[e]; }
        g_offsets[En] = off;
        int t = 0;
        for (int e = 0; e < En; e++) {
            for (int r = 0; r < g_counts[e]; r += TILE_M) {
                g_tile_expert[t]   = e;
                g_tile_rowstart[t] = g_offsets[e] + r;
                int rem = g_counts[e] - r;
                g_tile_rows[t]     = rem < TILE_M ? rem : TILE_M;
                t++;
            }
        }
        for (; t < MAX_TILES; t++) g_tile_rows[t] = 0;
    }
}

__global__ void scatter_kernel() {
    int t = blockIdx.x * blockDim.x + threadIdx.x;
    if (t < Bn) {
        int e = g_angle[t];
        int pos = atomicAdd(&g_cursor[e], 1);
        g_idx_sorted[g_offsets[e] + pos] = t;
    }
}

// ================= quant / conversion kernels =================
// x: per-row absmax -> two-level int8
__global__ __launch_bounds__(128) void qx_kernel(const float* __restrict__ x) {
    int row = blockIdx.x;
    int tid = threadIdx.x;
    const float* xr = x + (size_t)row * Dn;
    __shared__ float red[128];
    float vals[8];
    float m = 0.f;
#pragma unroll
    for (int i = 0; i < 8; i++) {
        vals[i] = xr[tid + i * 128];
        m = fmaxf(m, fabsf(vals[i]));
    }
    red[tid] = m;
    __syncthreads();
#pragma unroll
    for (int s = 64; s > 0; s >>= 1) {
        if (tid < s) red[tid] = fmaxf(red[tid], red[tid + s]);
        __syncthreads();
    }
    float mx = red[0];
    if (tid == 0) g_sa[row] = mx / QMAX;
    float inv = (mx > 0.f) ? QMAX / mx : 0.f;
#pragma unroll
    for (int i = 0; i < 8; i++) {
        char c1, c2;
        qsplit(vals[i], inv, c1, c2);
        g_x1[(size_t)row * Dn + tid + i * 128] = c1;
        g_x2[(size_t)row * Dn + tid + i * 128] = c2;
    }
}

// per-(e,n) column absmax of W1
__global__ __launch_bounds__(128) void qw1max_kernel(const float* __restrict__ W1) {
    int e = blockIdx.x;
    int n = blockIdx.y * 128 + threadIdx.x;
    float m = 0.f;
    if (n < Hn) {
        const float* W = W1 + (size_t)e * Dn * Hn + n;
#pragma unroll 8
        for (int k = 0; k < Dn; k++) m = fmaxf(m, fabsf(W[(size_t)k * Hn]));
    }
    g_sw1[e * NW + n] = m / QMAX;
    g_invw1[e * NW + n] = (m > 0.f) ? QMAX / m : 0.f;
}

// W1 [E][1024(k)][400(n)] -> int8 two-level [E][512(n)][1024(k)]
__global__ void qw1t_kernel(const float* __restrict__ W1) {
    __shared__ float t[32][33];
    int e = blockIdx.z, k0 = blockIdx.x * 32, n0 = blockIdx.y * 32;
    int tx = threadIdx.x, ty = threadIdx.y;   // 32 x 8
    const float* W = W1 + (size_t)e * Dn * Hn;
#pragma unroll
    for (int i = 0; i < 32; i += 8) {
        int k = k0 + ty + i, n = n0 + tx;
        t[ty + i][tx] = (n < Hn) ? W[(size_t)k * Hn + n] : 0.f;
    }
    __syncthreads();
#pragma unroll
    for (int i = 0; i < 32; i += 8) {
        int n = n0 + ty + i, k = k0 + tx;
        float v = t[tx][ty + i];
        float inv = g_invw1[e * NW + n];
        char c1, c2;
        qsplit(v, inv, c1, c2);
        size_t o = ((size_t)e * NW + n) * Dn + k;
        g_w1q1[o] = c1;
        g_w1q2[o] = c2;
    }
}

// W2 [E][400(k)][512(n)] -> bf16 hi/lo [E][512(n)][448(k)], k>=400 zero
__global__ void tw2_kernel(const float* __restrict__ W2) {
    __shared__ float t[32][33];
    int e = blockIdx.z, k0 = blockIdx.x * 32, n0 = blockIdx.y * 32;
    int tx = threadIdx.x, ty = threadIdx.y;
    const float* W = W2 + (size_t)e * Hn * K2n;
#pragma unroll
    for (int i = 0; i < 32; i += 8) {
        int k = k0 + ty + i, n = n0 + tx;
        t[ty + i][tx] = (k < Hn) ? W[(size_t)k * K2n + n] : 0.f;
    }
    __syncthreads();
    __nv_bfloat16* wh = reinterpret_cast<__nv_bfloat16*>(g_w2t_hi);
    __nv_bfloat16* wl = reinterpret_cast<__nv_bfloat16*>(g_w2t_lo);
#pragma unroll
    for (int i = 0; i < 32; i += 8) {
        int n = n0 + ty + i, k = k0 + tx;
        float v = t[tx][ty + i];
        __nv_bfloat16 h = __float2bfloat16(v);
        size_t o = ((size_t)e * NW + n) * HP + k;
        wh[o] = h;
        wl[o] = __float2bfloat16(v - __bfloat162float(h));
    }
}

// ================= GEMM1: int8 IMMA =================
// smem: [0,512) idx, [512,1024) bias, [1024,1536) sa, [1536,2048) sw
//       [2048..) two 24KB stages: X1@0 X2@6144 B1@12288 B2@18432 (48B row stride)
#define G1_STAGE 24576
#define G1_SMEM  (2048 + 2 * G1_STAGE)

__global__ __launch_bounds__(256) void gemm1_imma(const float* __restrict__ b1) {
    int bt = blockIdx.x;
    int rows = g_tile_rows[bt];
    if (rows == 0) return;
    int e  = g_tile_expert[bt];
    int rs = g_tile_rowstart[bt];
    int colbase = blockIdx.y * 128;

    extern __shared__ char smem[];
    uint32_t sb = smem_u32(smem);
    int tid = threadIdx.x;
    int wid = tid >> 5, lane = tid & 31;
    int wm = wid & 3, wn = wid >> 2;     // warp tile 32x64
    int tq = lane >> 2, tr = lane & 3;

    int*   idx_s  = reinterpret_cast<int*>(smem);
    float* bias_s = reinterpret_cast<float*>(smem + 512);
    float* sa_s   = reinterpret_cast<float*>(smem + 1024);
    float* sw_s   = reinterpret_cast<float*>(smem + 1536);
    if (tid < TILE_M) {
        int b = g_idx_sorted[rs + tid];
        idx_s[tid] = b;
        sa_s[tid] = g_sa[b];
        int col = colbase + tid;
        bias_s[tid] = (col < Hn) ? b1[e * Hn + col] : 0.f;
        sw_s[tid] = g_sw1[e * NW + col];
    }
    __syncthreads();

    const char* w1 = g_w1q1 + (size_t)e * NW * Dn;
    const char* w2 = g_w1q2 + (size_t)e * NW * Dn;

    auto fill = [&](int stg, int kt) {
#pragma unroll
        for (int i = tid; i < 1024; i += 256) {
            int arr = i >> 8;            // 0..3 (uniform per iteration)
            int r = (i >> 1) & 127;
            int half = i & 1;
            uint32_t dst = sb + 2048 + stg * G1_STAGE + arr * 6144 + r * 48 + half * 16;
            const char* src;
            if (arr == 0)      src = g_x1 + (size_t)idx_s[r] * Dn + kt * 32 + half * 16;
            else if (arr == 1) src = g_x2 + (size_t)idx_s[r] * Dn + kt * 32 + half * 16;
            else if (arr == 2) src = w1 + (size_t)(colbase + r) * Dn + kt * 32 + half * 16;
            else               src = w2 + (size_t)(colbase + r) * Dn + kt * 32 + half * 16;
            CP16(dst, src);
        }
    };

    int acc1[2][8][4], acc2[2][8][4];
#pragma unroll
    for (int mt = 0; mt < 2; mt++)
#pragma unroll
        for (int nt = 0; nt < 8; nt++)
#pragma unroll
            for (int j = 0; j < 4; j++) { acc1[mt][nt][j] = 0; acc2[mt][nt][j] = 0; }

    fill(0, 0); CP_COMMIT();
    for (int it = 0; it < 32; it++) {
        if (it + 1 < 32) { fill((it + 1) & 1, it + 1); CP_COMMIT(); CP_WAIT1(); }
        else CP_WAIT0();
        __syncthreads();
        const char* st = smem + 2048 + (it & 1) * G1_STAGE;
        int kb = tr * 4;
        uint32_t a1[2][4], a2[2][4], bf[8][2];
#pragma unroll
        for (int mt = 0; mt < 2; mt++) {
            int r0 = wm * 32 + mt * 16 + tq;
            a1[mt][0] = *(const uint32_t*)(st + r0 * 48 + kb);
            a1[mt][1] = *(const uint32_t*)(st + (r0 + 8) * 48 + kb);
            a1[mt][2] = *(const uint32_t*)(st + r0 * 48 + kb + 16);
            a1[mt][3] = *(const uint32_t*)(st + (r0 + 8) * 48 + kb + 16);
            a2[mt][0] = *(const uint32_t*)(st + 6144 + r0 * 48 + kb);
            a2[mt][1] = *(const uint32_t*)(st + 6144 + (r0 + 8) * 48 + kb);
            a2[mt][2] = *(const uint32_t*)(st + 6144 + r0 * 48 + kb + 16);
            a2[mt][3] = *(const uint32_t*)(st + 6144 + (r0 + 8) * 48 + kb + 16);
        }
#pragma unroll
        for (int nt = 0; nt < 8; nt++) {
            int n = wn * 64 + nt * 8 + tq;
            bf[nt][0] = *(const uint32_t*)(st + 12288 + n * 48 + kb);
            bf[nt][1] = *(const uint32_t*)(st + 12288 + n * 48 + kb + 16);
        }
#pragma unroll
        for (int mt = 0; mt < 2; mt++)
#pragma unroll
            for (int nt = 0; nt < 8; nt++) {
                imma16832(acc1[mt][nt], a1[mt], bf[nt]);   // S11
                imma16832(acc2[mt][nt], a2[mt], bf[nt]);   // S21
            }
#pragma unroll
        for (int nt = 0; nt < 8; nt++) {
            int n = wn * 64 + nt * 8 + tq;
            bf[nt][0] = *(const uint32_t*)(st + 18432 + n * 48 + kb);
            bf[nt][1] = *(const uint32_t*)(st + 18432 + n * 48 + kb + 16);
        }
#pragma unroll
        for (int mt = 0; mt < 2; mt++)
#pragma unroll
            for (int nt = 0; nt < 8; nt++)
                imma16832(acc2[mt][nt], a1[mt], bf[nt]);   // S12
        __syncthreads();
    }

    // epilogue: combine scales + bias + relu + bf16 split -> h1
    uint32_t* h1h = reinterpret_cast<uint32_t*>(g_h1_hi);
    uint32_t* h1l = reinterpret_cast<uint32_t*>(g_h1_lo);
#pragma unroll
    for (int mt = 0; mt < 2; mt++) {
        int r0 = wm * 32 + mt * 16 + tq;
#pragma unroll
        for (int nt = 0; nt < 8; nt++) {
            int c = wn * 64 + nt * 8 + tr * 2;
            int gcol = colbase + c;
            if (gcol >= HP) continue;
#pragma unroll
            for (int half = 0; half < 2; half++) {
                int r = r0 + half * 8;
                if (r >= rows) continue;
                float s = sa_s[r];
                float f0 = 16384.f * (float)acc1[mt][nt][half * 2]
                         + 128.f * (float)acc2[mt][nt][half * 2];
                float f1 = 16384.f * (float)acc1[mt][nt][half * 2 + 1]
                         + 128.f * (float)acc2[mt][nt][half * 2 + 1];
                float v0 = (gcol < Hn)     ? fmaxf(f0 * s * sw_s[c]     + bias_s[c], 0.f)     : 0.f;
                float v1 = (gcol + 1 < Hn) ? fmaxf(f1 * s * sw_s[c + 1] + bias_s[c + 1], 0.f) : 0.f;
                uint32_t hi, lo;
                split2(v0, v1, hi, lo);
                size_t o = ((size_t)(rs + r) * HP + gcol) >> 1;
                h1h[o] = hi;
                h1l[o] = lo;
            }
        }
    }
}

// ================= GEMM2: bf16 3-pass (unchanged from R4) =================
#define STAGE_SZ 40960
#define SMEM_SZ  (1024 + 2 * STAGE_SZ)

__global__ __launch_bounds__(256) void gemm2_mma(const float* __restrict__ b2,
                                                 float* __restrict__ out) {
    int bt = blockIdx.x;
    int rows = g_tile_rows[bt];
    if (rows == 0) return;
    int e  = g_tile_expert[bt];
    int rs = g_tile_rowstart[bt];
    int colbase = blockIdx.y * 128;

    extern __shared__ char smem[];
    uint32_t sb = smem_u32(smem);
    int tid = threadIdx.x;
    int wid = tid >> 5, lane = tid & 31;
    int wm = wid & 3, wn = wid >> 2;
    int tq = lane >> 2, tr = lane & 3;

    int* idx_s = reinterpret_cast<int*>(smem);
    float* bias_s = reinterpret_cast<float*>(smem + 512);
    if (tid < TILE_M) idx_s[tid] = g_idx_sorted[rs + tid];
    if (tid < 128) bias_s[tid] = b2[e * K2n + colbase + tid];
    __syncthreads();

    const uint4* w2h = g_w2t_hi + (size_t)e * NW * (HP / 8);
    const uint4* w2l = g_w2t_lo + (size_t)e * NW * (HP / 8);

    auto fill = [&](int stg, int kt) {
        uint32_t base = sb + 1024 + stg * STAGE_SZ;
#pragma unroll
        for (int i = tid; i < 512; i += 256) {
            int r = i >> 2, c4 = i & 3;
            uint32_t dA = base + r * 80 + c4 * 16;
            size_t ao = (size_t)(rs + r) * (HP / 8) + kt * 4 + c4;
            CP16(dA,         g_h1_hi + ao);
            CP16(dA + 10240, g_h1_lo + ao);
            uint32_t dB = base + 20480 + r * 80 + c4 * 16;
            size_t bo = (size_t)(colbase + r) * (HP / 8) + kt * 4 + c4;
            CP16(dB,         w2h + bo);
            CP16(dB + 10240, w2l + bo);
        }
    };

    float acc[2][8][4];
#pragma unroll
    for (int mt = 0; mt < 2; mt++)
#pragma unroll
        for (int nt = 0; nt < 8; nt++)
#pragma unroll
            for (int j = 0; j < 4; j++) acc[mt][nt][j] = 0.f;

    fill(0, 0); CP_COMMIT();
    for (int it = 0; it < 14; it++) {
        if (it + 1 < 14) { fill((it + 1) & 1, it + 1); CP_COMMIT(); CP_WAIT1(); }
        else CP_WAIT0();
        __syncthreads();
        const char* st = smem + 1024 + (it & 1) * STAGE_SZ;
#pragma unroll
        for (int ks = 0; ks < 2; ks++) {
            const char* As = st;
            const char* Bs = st + 20480;
            int kb = ks * 32 + tr * 4;
            uint32_t ah[2][4], al[2][4], bb[8][2];
#pragma unroll
            for (int mt = 0; mt < 2; mt++) {
                int r0 = wm * 32 + mt * 16 + tq;
                ah[mt][0] = *(const uint32_t*)(As + r0 * 80 + kb);
                ah[mt][1] = *(const uint32_t*)(As + (r0 + 8) * 80 + kb);
                ah[mt][2] = *(const uint32_t*)(As + r0 * 80 + kb + 16);
                ah[mt][3] = *(const uint32_t*)(As + (r0 + 8) * 80 + kb + 16);
                al[mt][0] = *(const uint32_t*)(As + 10240 + r0 * 80 + kb);
                al[mt][1] = *(const uint32_t*)(As + 10240 + (r0 + 8) * 80 + kb);
                al[mt][2] = *(const uint32_t*)(As + 10240 + r0 * 80 + kb + 16);
                al[mt][3] = *(const uint32_t*)(As + 10240 + (r0 + 8) * 80 + kb + 16);
            }
#pragma unroll
            for (int nt = 0; nt < 8; nt++) {
                int n = wn * 64 + nt * 8 + tq;
                bb[nt][0] = *(const uint32_t*)(Bs + n * 80 + kb);
                bb[nt][1] = *(const uint32_t*)(Bs + n * 80 + kb + 16);
            }
#pragma unroll
            for (int mt = 0; mt < 2; mt++)
#pragma unroll
                for (int nt = 0; nt < 8; nt++) {
                    mma16816(acc[mt][nt], ah[mt], bb[nt]);
                    mma16816(acc[mt][nt], al[mt], bb[nt]);
                }
#pragma unroll
            for (int nt = 0; nt < 8; nt++) {
                int n = wn * 64 + nt * 8 + tq;
                bb[nt][0] = *(const uint32_t*)(Bs + 10240 + n * 80 + kb);
                bb[nt][1] = *(const uint32_t*)(Bs + 10240 + n * 80 + kb + 16);
            }
#pragma unroll
            for (int mt = 0; mt < 2; mt++)
#pragma unroll
                for (int nt = 0; nt < 8; nt++)
                    mma16816(acc[mt][nt], ah[mt], bb[nt]);
        }
        __syncthreads();
    }

#pragma unroll
    for (int mt = 0; mt < 2; mt++) {
        int r0 = wm * 32 + mt * 16 + tq;
#pragma unroll
        for (int nt = 0; nt < 8; nt++) {
            int c = wn * 64 + nt * 8 + tr * 2;
            int gcol = colbase + c;
#pragma unroll
            for (int half = 0; half < 2; half++) {
                int r = r0 + half * 8;
                if (r >= rows) continue;
                int b = idx_s[r];
                float2 v;
                v.x = acc[mt][nt][half * 2]     + bias_s[c];
                v.y = acc[mt][nt][half * 2 + 1] + bias_s[c + 1];
                float* dst = (gcol < Ln)
                    ? out + (size_t)b * Ln + gcol
                    : out + (size_t)Bn * Ln + (size_t)b * Ln + (gcol - Ln);
                *reinterpret_cast<float2*>(dst) = v;
            }
        }
    }
}

// ================= launch =================
extern "C" void kernel_launch(void* const* d_in, const int* in_sizes, int n_in,
                              void* d_out, int out_size) {
    const float* x  = (const float*)d_in[0];
    const void*  ai = d_in[1];
    const float* W1 = (const float*)d_in[2];
    const float* b1 = (const float*)d_in[3];
    const float* W2 = (const float*)d_in[4];
    const float* b2 = (const float*)d_in[5];
    float* out = (float*)d_out;

    cudaFuncSetAttribute(gemm1_imma, cudaFuncAttributeMaxDynamicSharedMemorySize, G1_SMEM);
    cudaFuncSetAttribute(gemm2_mma, cudaFuncAttributeMaxDynamicSharedMemorySize, SMEM_SZ);

    reset_kernel<<<1, 128>>>();
    detect_kernel<<<(Bn / 2 + 255) / 256, 256>>>((const long long*)ai);
    convert_count_kernel<<<(Bn + 255) / 256, 256>>>(ai);
    prefix_kernel<<<1, 1>>>();
    scatter_kernel<<<(Bn + 255) / 256, 256>>>();

    qx_kernel<<<Bn, 128>>>(x);
    qw1max_kernel<<<dim3(En, 4), 128>>>(W1);
    qw1t_kernel<<<dim3(Dn / 32, NW / 32, En), dim3(32, 8)>>>(W1);
    tw2_kernel<<<dim3(HP / 32, NW / 32, En), dim3(32, 8)>>>(W2);

    gemm1_imma<<<dim3(MAX_TILES, 4), 256, G1_SMEM>>>(b1);
    gemm2_mma<<<dim3(MAX_TILES, 4), 256, SMEM_SZ>>>(b2, out);
}

// round 6
// speedup vs baseline: 2.3559x; 2.3559x over previous
#include <cuda_runtime.h>
#include <cuda_bf16.h>
#include <cstdint>

// Problem constants
constexpr int Bn = 8192;   // batch
constexpr int Dn = 1024;   // input dim (K1)
constexpr int Hn = 400;    // hidden
constexpr int Ln = 256;    // half output
constexpr int En = 16;     // experts
constexpr int K2n = 512;   // 2L (N of GEMM2)
constexpr int HP = 416;    // hidden padded to 13*32 (K of GEMM2)
constexpr int NW = 512;    // padded N rows for transposed weights

#define TILE_M 128
#define MAX_TILES 96       // >= B/128 + E = 80
#define NT1 80             // GEMM1 N-tile (5 tiles * 80 = 400 exact)

// ================= device scratch (zero-init, no allocs) =================
__device__ int   g_counts[En];
__device__ int   g_offsets[En + 1];
__device__ int   g_cursor[En];
__device__ int   g_is64;
__device__ int   g_angle[Bn];
__device__ int   g_idx_sorted[Bn + TILE_M];
__device__ int   g_tile_expert[MAX_TILES];
__device__ int   g_tile_rowstart[MAX_TILES];
__device__ int   g_tile_rows[MAX_TILES];

// bf16 hi/lo buffers, uint4 for 16B alignment
__device__ uint4 g_x_hi[(size_t)Bn * Dn / 8];              // [Bn][1024] bf16
__device__ uint4 g_x_lo[(size_t)Bn * Dn / 8];
__device__ uint4 g_w1t_hi[(size_t)En * NW * Dn / 8];       // [E][512][1024] (n,k); rows 0..415 filled
__device__ uint4 g_w1t_lo[(size_t)En * NW * Dn / 8];
__device__ uint4 g_w2t_hi[(size_t)En * NW * HP / 8];       // [E][512][416] (n,k)
__device__ uint4 g_w2t_lo[(size_t)En * NW * HP / 8];
__device__ uint4 g_h1_hi[(size_t)(Bn + TILE_M) * HP / 8];  // [rows][416]
__device__ uint4 g_h1_lo[(size_t)(Bn + TILE_M) * HP / 8];

// ================= helpers =================
__device__ __forceinline__ uint32_t smem_u32(const void* p) {
    uint32_t a;
    asm("{ .reg .u64 t; cvta.to.shared.u64 t, %1; cvt.u32.u64 %0, t; }" : "=r"(a) : "l"(p));
    return a;
}

#define CP16(dst_u32, src_ptr) \
    asm volatile("cp.async.cg.shared.global [%0], [%1], 16;" :: "r"(dst_u32), "l"(src_ptr))
#define CP_COMMIT() asm volatile("cp.async.commit_group;" ::: "memory")
#define CP_WAIT1()  asm volatile("cp.async.wait_group 1;" ::: "memory")
#define CP_WAIT0()  asm volatile("cp.async.wait_group 0;" ::: "memory")

__device__ __forceinline__ void mma16816(float* d, const uint32_t* a, const uint32_t* b) {
    asm volatile(
        "mma.sync.aligned.m16n8k16.row.col.f32.bf16.bf16.f32 "
        "{%0,%1,%2,%3}, {%4,%5,%6,%7}, {%8,%9}, {%0,%1,%2,%3};"
        : "+f"(d[0]), "+f"(d[1]), "+f"(d[2]), "+f"(d[3])
        : "r"(a[0]), "r"(a[1]), "r"(a[2]), "r"(a[3]), "r"(b[0]), "r"(b[1]));
}

__device__ __forceinline__ void split2(float v0, float v1, uint32_t& hi, uint32_t& lo) {
    __nv_bfloat16 h0 = __float2bfloat16(v0);
    __nv_bfloat16 h1 = __float2bfloat16(v1);
    __nv_bfloat16 l0 = __float2bfloat16(v0 - __bfloat162float(h0));
    __nv_bfloat16 l1 = __float2bfloat16(v1 - __bfloat162float(h1));
    __nv_bfloat162 ph; ph.x = h0; ph.y = h1;
    __nv_bfloat162 pl; pl.x = l0; pl.y = l1;
    hi = *reinterpret_cast<uint32_t*>(&ph);
    lo = *reinterpret_cast<uint32_t*>(&pl);
}

// ================= prep kernels =================
// merged reset + int64/int32 detect (one block)
__global__ __launch_bounds__(1024) void init_detect_kernel(const long long* __restrict__ ai) {
    int t = threadIdx.x;
    if (t < En) { g_counts[t] = 0; g_cursor[t] = 0; }
    if (t == 0) g_is64 = 1;
    if (t < TILE_M) g_idx_sorted[Bn + t] = 0;
    __syncthreads();
    for (int i = t; i < Bn / 2; i += 1024) {
        long long v = ai[i];
        if (v < 0 || v >= En) g_is64 = 0;
    }
}

__global__ void convert_count_kernel(const void* __restrict__ ai) {
    int t = blockIdx.x * blockDim.x + threadIdx.x;
    if (t < Bn) {
        int v = g_is64 ? (int)((const long long*)ai)[t] : ((const int*)ai)[t];
        g_angle[t] = v;
        atomicAdd(&g_counts[v], 1);
    }
}

// parallel prefix + tile-list build (one block of 128)
__global__ __launch_bounds__(128) void prefix_kernel() {
    int t = threadIdx.x;
    if (t < MAX_TILES) g_tile_rows[t] = 0;
    __syncthreads();
    if (t < En) {
        int off = 0, tbase = 0;
        for (int i = 0; i < t; i++) {
            off += g_counts[i];
            tbase += (g_counts[i] + TILE_M - 1) / TILE_M;
        }
        g_offsets[t] = off;
        if (t == En - 1) g_offsets[En] = off + g_counts[t];
        int nt = (g_counts[t] + TILE_M - 1) / TILE_M;
        for (int k = 0; k < nt; k++) {
            g_tile_expert[tbase + k]   = t;
            g_tile_rowstart[tbase + k] = off + k * TILE_M;
            int rem = g_counts[t] - k * TILE_M;
            g_tile_rows[tbase + k]     = rem < TILE_M ? rem : TILE_M;
        }
    }
}

__global__ void scatter_kernel() {
    int t = blockIdx.x * blockDim.x + threadIdx.x;
    if (t < Bn) {
        int e = g_angle[t];
        int pos = atomicAdd(&g_cursor[e], 1);
        g_idx_sorted[g_offsets[e] + pos] = t;
    }
}

// ================= conversions =================
// x split + h1 pad-column zeroing (cols 400..415 of every h1 row)
__global__ void split_x_kernel(const float* __restrict__ x) {
    int i = blockIdx.x * blockDim.x + threadIdx.x;
    if (i < Bn * Dn / 4) {
        float4 v = reinterpret_cast<const float4*>(x)[i];
        uint32_t h0, l0, h1, l1;
        split2(v.x, v.y, h0, l0);
        split2(v.z, v.w, h1, l1);
        uint32_t* xh = reinterpret_cast<uint32_t*>(g_x_hi);
        uint32_t* xl = reinterpret_cast<uint32_t*>(g_x_lo);
        xh[i * 2] = h0; xh[i * 2 + 1] = h1;
        xl[i * 2] = l0; xl[i * 2 + 1] = l1;
    }
    // zero h1 pad: (Bn+TILE_M) rows x 16 bf16 = 8 uint32 per row
    if (i < (Bn + TILE_M) * 8) {
        int row = i >> 3, c = i & 7;
        uint32_t* h1h = reinterpret_cast<uint32_t*>(g_h1_hi);
        uint32_t* h1l = reinterpret_cast<uint32_t*>(g_h1_lo);
        size_t o = (size_t)row * (HP / 2) + 200 + c;   // (row*416+400)/2 + c
        h1h[o] = 0;
        h1l[o] = 0;
    }
}

// W1 [E][1024(k)][400(n)] -> [E][512(n)][1024(k)] hi/lo, rows 0..415 (n>=400 zero)
__global__ void tw1_kernel(const float* __restrict__ W1) {
    __shared__ float t[32][33];
    int e = blockIdx.z, k0 = blockIdx.x * 32, n0 = blockIdx.y * 32;
    int tx = threadIdx.x, ty = threadIdx.y;   // 32 x 8
    const float* W = W1 + (size_t)e * Dn * Hn;
#pragma unroll
    for (int i = 0; i < 32; i += 8) {
        int k = k0 + ty + i, n = n0 + tx;
        t[ty + i][tx] = (n < Hn) ? W[(size_t)k * Hn + n] : 0.f;
    }
    __syncthreads();
    __nv_bfloat16* wh = reinterpret_cast<__nv_bfloat16*>(g_w1t_hi);
    __nv_bfloat16* wl = reinterpret_cast<__nv_bfloat16*>(g_w1t_lo);
#pragma unroll
    for (int i = 0; i < 32; i += 8) {
        int n = n0 + ty + i, k = k0 + tx;
        float v = t[tx][ty + i];
        __nv_bfloat16 h = __float2bfloat16(v);
        size_t o = ((size_t)e * NW + n) * Dn + k;
        wh[o] = h;
        wl[o] = __float2bfloat16(v - __bfloat162float(h));
    }
}

// W2 [E][400(k)][512(n)] -> [E][512(n)][416(k)] hi/lo, k>=400 zero
__global__ void tw2_kernel(const float* __restrict__ W2) {
    __shared__ float t[32][33];
    int e = blockIdx.z, k0 = blockIdx.x * 32, n0 = blockIdx.y * 32;
    int tx = threadIdx.x, ty = threadIdx.y;
    const float* W = W2 + (size_t)e * Hn * K2n;
#pragma unroll
    for (int i = 0; i < 32; i += 8) {
        int k = k0 + ty + i, n = n0 + tx;
        t[ty + i][tx] = (k < Hn) ? W[(size_t)k * K2n + n] : 0.f;
    }
    __syncthreads();
    __nv_bfloat16* wh = reinterpret_cast<__nv_bfloat16*>(g_w2t_hi);
    __nv_bfloat16* wl = reinterpret_cast<__nv_bfloat16*>(g_w2t_lo);
#pragma unroll
    for (int i = 0; i < 32; i += 8) {
        int n = n0 + ty + i, k = k0 + tx;
        float v = t[tx][ty + i];
        __nv_bfloat16 h = __float2bfloat16(v);
        size_t o = ((size_t)e * NW + n) * HP + k;
        wh[o] = h;
        wl[o] = __float2bfloat16(v - __bfloat162float(h));
    }
}

// ================= GEMM1: bf16 3-pass, tile 128x80 =================
// smem: [0,512) idx, [512,896) bias, [1024..) two stages
// stage rows (stride 80B, 64B data): Ahi r0-127 @0, Alo r128-255 @10240,
//                                    Bhi r256-335 @20480, Blo r336-415 @26880
#define G1_STAGE 33280     // 416 * 80
#define G1_SMEM  (1024 + 2 * G1_STAGE)

__global__ __launch_bounds__(256) void gemm1_mma(const float* __restrict__ b1) {
    int bt = blockIdx.x;
    int rows = g_tile_rows[bt];
    if (rows == 0) return;
    int e  = g_tile_expert[bt];
    int rs = g_tile_rowstart[bt];
    int colbase = blockIdx.y * NT1;

    extern __shared__ char smem[];
    uint32_t sb = smem_u32(smem);
    int tid = threadIdx.x;
    int wid = tid >> 5, lane = tid & 31;
    int wm = wid & 3, wn = wid >> 2;      // warps: 4 (M) x 2 (N); warp tile 32x40
    int tq = lane >> 2, tr = lane & 3;

    int* idx_s = reinterpret_cast<int*>(smem);
    float* bias_s = reinterpret_cast<float*>(smem + 512);
    if (tid < TILE_M) idx_s[tid] = g_idx_sorted[rs + tid];
    if (tid < NT1) bias_s[tid] = b1[e * Hn + colbase + tid];
    __syncthreads();

    const uint4* w1h = g_w1t_hi + (size_t)e * NW * (Dn / 8);
    const uint4* w1l = g_w1t_lo + (size_t)e * NW * (Dn / 8);

    auto fill = [&](int stg, int kt) {
        uint32_t base = sb + 1024 + stg * G1_STAGE;
#pragma unroll
        for (int i = tid; i < 512; i += 256) {        // A hi/lo: 128 rows x 4 uint4
            int r = i >> 2, c4 = i & 3;
            uint32_t d = base + r * 80 + c4 * 16;
            size_t ao = (size_t)idx_s[r] * 128 + kt * 4 + c4;
            CP16(d,         g_x_hi + ao);
            CP16(d + 10240, g_x_lo + ao);
        }
#pragma unroll
        for (int i = tid; i < 320; i += 256) {        // B hi/lo: 80 rows x 4 uint4
            int r = i >> 2, c4 = i & 3;
            uint32_t d = base + 20480 + r * 80 + c4 * 16;
            size_t bo = (size_t)(colbase + r) * 128 + kt * 4 + c4;
            CP16(d,        w1h + bo);
            CP16(d + 6400, w1l + bo);
        }
    };

    float acc[2][5][4];
#pragma unroll
    for (int mt = 0; mt < 2; mt++)
#pragma unroll
        for (int nt = 0; nt < 5; nt++)
#pragma unroll
            for (int j = 0; j < 4; j++) acc[mt][nt][j] = 0.f;

    fill(0, 0); CP_COMMIT();
    for (int it = 0; it < 32; it++) {
        if (it + 1 < 32) { fill((it + 1) & 1, it + 1); CP_COMMIT(); CP_WAIT1(); }
        else CP_WAIT0();
        __syncthreads();
        const char* st = smem + 1024 + (it & 1) * G1_STAGE;
#pragma unroll
        for (int ks = 0; ks < 2; ks++) {
            int kb = ks * 32 + tr * 4;
            uint32_t ah[2][4], al[2][4], bb[5][2];
#pragma unroll
            for (int mt = 0; mt < 2; mt++) {
                int r0 = wm * 32 + mt * 16 + tq;
                ah[mt][0] = *(const uint32_t*)(st + r0 * 80 + kb);
                ah[mt][1] = *(const uint32_t*)(st + (r0 + 8) * 80 + kb);
                ah[mt][2] = *(const uint32_t*)(st + r0 * 80 + kb + 16);
                ah[mt][3] = *(const uint32_t*)(st + (r0 + 8) * 80 + kb + 16);
                al[mt][0] = *(const uint32_t*)(st + 10240 + r0 * 80 + kb);
                al[mt][1] = *(const uint32_t*)(st + 10240 + (r0 + 8) * 80 + kb);
                al[mt][2] = *(const uint32_t*)(st + 10240 + r0 * 80 + kb + 16);
                al[mt][3] = *(const uint32_t*)(st + 10240 + (r0 + 8) * 80 + kb + 16);
            }
#pragma unroll
            for (int nt = 0; nt < 5; nt++) {
                int n = wn * 40 + nt * 8 + tq;
                bb[nt][0] = *(const uint32_t*)(st + 20480 + n * 80 + kb);
                bb[nt][1] = *(const uint32_t*)(st + 20480 + n * 80 + kb + 16);
            }
#pragma unroll
            for (int mt = 0; mt < 2; mt++)
#pragma unroll
                for (int nt = 0; nt < 5; nt++) {
                    mma16816(acc[mt][nt], ah[mt], bb[nt]);   // hh
                    mma16816(acc[mt][nt], al[mt], bb[nt]);   // lh
                }
#pragma unroll
            for (int nt = 0; nt < 5; nt++) {
                int n = wn * 40 + nt * 8 + tq;
                bb[nt][0] = *(const uint32_t*)(st + 26880 + n * 80 + kb);
                bb[nt][1] = *(const uint32_t*)(st + 26880 + n * 80 + kb + 16);
            }
#pragma unroll
            for (int mt = 0; mt < 2; mt++)
#pragma unroll
                for (int nt = 0; nt < 5; nt++)
                    mma16816(acc[mt][nt], ah[mt], bb[nt]);   // hl
        }
        __syncthreads();
    }

    // epilogue: bias + relu + bf16 split -> h1 (all 80 cols real)
    uint32_t* h1h = reinterpret_cast<uint32_t*>(g_h1_hi);
    uint32_t* h1l = reinterpret_cast<uint32_t*>(g_h1_lo);
#pragma unroll
    for (int mt = 0; mt < 2; mt++) {
        int r0 = wm * 32 + mt * 16 + tq;
#pragma unroll
        for (int nt = 0; nt < 5; nt++) {
            int c = wn * 40 + nt * 8 + tr * 2;
            int gcol = colbase + c;
#pragma unroll
            for (int half = 0; half < 2; half++) {
                int r = r0 + half * 8;
                if (r >= rows) continue;
                float v0 = fmaxf(acc[mt][nt][half * 2]     + bias_s[c], 0.f);
                float v1 = fmaxf(acc[mt][nt][half * 2 + 1] + bias_s[c + 1], 0.f);
                uint32_t hi, lo;
                split2(v0, v1, hi, lo);
                size_t o = ((size_t)(rs + r) * HP + gcol) >> 1;
                h1h[o] = hi;
                h1l[o] = lo;
            }
        }
    }
}

// ================= GEMM2: bf16 3-pass, tile 128x128, K=416 =================
#define STAGE_SZ 40960
#define SMEM_SZ  (1024 + 2 * STAGE_SZ)

__global__ __launch_bounds__(256) void gemm2_mma(const float* __restrict__ b2,
                                                 float* __restrict__ out) {
    int bt = blockIdx.x;
    int rows = g_tile_rows[bt];
    if (rows == 0) return;
    int e  = g_tile_expert[bt];
    int rs = g_tile_rowstart[bt];
    int colbase = blockIdx.y * 128;

    extern __shared__ char smem[];
    uint32_t sb = smem_u32(smem);
    int tid = threadIdx.x;
    int wid = tid >> 5, lane = tid & 31;
    int wm = wid & 3, wn = wid >> 2;
    int tq = lane >> 2, tr = lane & 3;

    int* idx_s = reinterpret_cast<int*>(smem);
    float* bias_s = reinterpret_cast<float*>(smem + 512);
    if (tid < TILE_M) idx_s[tid] = g_idx_sorted[rs + tid];
    if (tid < 128) bias_s[tid] = b2[e * K2n + colbase + tid];
    __syncthreads();

    const uint4* w2h = g_w2t_hi + (size_t)e * NW * (HP / 8);
    const uint4* w2l = g_w2t_lo + (size_t)e * NW * (HP / 8);

    auto fill = [&](int stg, int kt) {
        uint32_t base = sb + 1024 + stg * STAGE_SZ;
#pragma unroll
        for (int i = tid; i < 512; i += 256) {
            int r = i >> 2, c4 = i & 3;
            uint32_t dA = base + r * 80 + c4 * 16;
            size_t ao = (size_t)(rs + r) * (HP / 8) + kt * 4 + c4;
            CP16(dA,         g_h1_hi + ao);
            CP16(dA + 10240, g_h1_lo + ao);
            uint32_t dB = base + 20480 + r * 80 + c4 * 16;
            size_t bo = (size_t)(colbase + r) * (HP / 8) + kt * 4 + c4;
            CP16(dB,         w2h + bo);
            CP16(dB + 10240, w2l + bo);
        }
    };

    float acc[2][8][4];
#pragma unroll
    for (int mt = 0; mt < 2; mt++)
#pragma unroll
        for (int nt = 0; nt < 8; nt++)
#pragma unroll
            for (int j = 0; j < 4; j++) acc[mt][nt][j] = 0.f;

    fill(0, 0); CP_COMMIT();
    for (int it = 0; it < 13; it++) {
        if (it + 1 < 13) { fill((it + 1) & 1, it + 1); CP_COMMIT(); CP_WAIT1(); }
        else CP_WAIT0();
        __syncthreads();
        const char* st = smem + 1024 + (it & 1) * STAGE_SZ;
#pragma unroll
        for (int ks = 0; ks < 2; ks++) {
            const char* As = st;
            const char* Bs = st + 20480;
            int kb = ks * 32 + tr * 4;
            uint32_t ah[2][4], al[2][4], bb[8][2];
#pragma unroll
            for (int mt = 0; mt < 2; mt++) {
                int r0 = wm * 32 + mt * 16 + tq;
                ah[mt][0] = *(const uint32_t*)(As + r0 * 80 + kb);
                ah[mt][1] = *(const uint32_t*)(As + (r0 + 8) * 80 + kb);
                ah[mt][2] = *(const uint32_t*)(As + r0 * 80 + kb + 16);
                ah[mt][3] = *(const uint32_t*)(As + (r0 + 8) * 80 + kb + 16);
                al[mt][0] = *(const uint32_t*)(As + 10240 + r0 * 80 + kb);
                al[mt][1] = *(const uint32_t*)(As + 10240 + (r0 + 8) * 80 + kb);
                al[mt][2] = *(const uint32_t*)(As + 10240 + r0 * 80 + kb + 16);
                al[mt][3] = *(const uint32_t*)(As + 10240 + (r0 + 8) * 80 + kb + 16);
            }
#pragma unroll
            for (int nt = 0; nt < 8; nt++) {
                int n = wn * 64 + nt * 8 + tq;
                bb[nt][0] = *(const uint32_t*)(Bs + n * 80 + kb);
                bb[nt][1] = *(const uint32_t*)(Bs + n * 80 + kb + 16);
            }
#pragma unroll
            for (int mt = 0; mt < 2; mt++)
#pragma unroll
                for (int nt = 0; nt < 8; nt++) {
                    mma16816(acc[mt][nt], ah[mt], bb[nt]);
                    mma16816(acc[mt][nt], al[mt], bb[nt]);
                }
#pragma unroll
            for (int nt = 0; nt < 8; nt++) {
                int n = wn * 64 + nt * 8 + tq;
                bb[nt][0] = *(const uint32_t*)(Bs + 10240 + n * 80 + kb);
                bb[nt][1] = *(const uint32_t*)(Bs + 10240 + n * 80 + kb + 16);
            }
#pragma unroll
            for (int mt = 0; mt < 2; mt++)
#pragma unroll
                for (int nt = 0; nt < 8; nt++)
                    mma16816(acc[mt][nt], ah[mt], bb[nt]);
        }
        __syncthreads();
    }

#pragma unroll
    for (int mt = 0; mt < 2; mt++) {
        int r0 = wm * 32 + mt * 16 + tq;
#pragma unroll
        for (int nt = 0; nt < 8; nt++) {
            int c = wn * 64 + nt * 8 + tr * 2;
            int gcol = colbase + c;
#pragma unroll
            for (int half = 0; half < 2; half++) {
                int r = r0 + half * 8;
                if (r >= rows) continue;
                int b = idx_s[r];
                float2 v;
                v.x = acc[mt][nt][half * 2]     + bias_s[c];
                v.y = acc[mt][nt][half * 2 + 1] + bias_s[c + 1];
                float* dst = (gcol < Ln)
                    ? out + (size_t)b * Ln + gcol
                    : out + (size_t)Bn * Ln + (size_t)b * Ln + (gcol - Ln);
                *reinterpret_cast<float2*>(dst) = v;
            }
        }
    }
}

// ================= launch =================
extern "C" void kernel_launch(void* const* d_in, const int* in_sizes, int n_in,
                              void* d_out, int out_size) {
    const float* x  = (const float*)d_in[0];
    const void*  ai = d_in[1];
    const float* W1 = (const float*)d_in[2];
    const float* b1 = (const float*)d_in[3];
    const float* W2 = (const float*)d_in[4];
    const float* b2 = (const float*)d_in[5];
    float* out = (float*)d_out;

    cudaFuncSetAttribute(gemm1_mma, cudaFuncAttributeMaxDynamicSharedMemorySize, G1_SMEM);
    cudaFuncSetAttribute(gemm2_mma, cudaFuncAttributeMaxDynamicSharedMemorySize, SMEM_SZ);

    init_detect_kernel<<<1, 1024>>>((const long long*)ai);
    convert_count_kernel<<<(Bn + 255) / 256, 256>>>(ai);
    prefix_kernel<<<1, 128>>>();
    scatter_kernel<<<(Bn + 255) / 256, 256>>>();

    split_x_kernel<<<(Bn * Dn / 4 + 255) / 256, 256>>>(x);
    tw1_kernel<<<dim3(Dn / 32, 13, En), dim3(32, 8)>>>(W1);
    tw2_kernel<<<dim3(HP / 32, NW / 32, En), dim3(32, 8)>>>(W2);

    gemm1_mma<<<dim3(MAX_TILES, 5), 256, G1_SMEM>>>(b1);
    gemm2_mma<<<dim3(MAX_TILES, 4), 256, SMEM_SZ>>>(b2, out);
}